// round 1
// baseline (speedup 1.0000x reference)
#include <cuda_runtime.h>
#include <math.h>

// ---------------------------------------------------------------------------
// QRNN: gates = causal conv1d(window=2) over x  -> tanh/sigmoid/sigmoid
//       then fo-pool scan: c_t = f*c_{t-1} + (1-f)*z ; y = o*c
// Shapes: x[8,4096,512], kernel[2,512,1536], bias[1536], out[8,4096,512]
// ---------------------------------------------------------------------------

#define B_   8
#define T_   4096
#define D_   512
#define U_   512
#define N3_  1536          // 3*U
#define K_   1024          // WINDOW*D
#define M_   (B_*T_)       // 32768

// GEMM tile config
#define BM 64
#define BN 64
#define BK 16
#define ASTRIDE 68         // padded stride for As (bank-conflict mitigation, 16B aligned)

// scan config
#define NCHUNK 32
#define TCHUNK (T_ / NCHUNK)   // 128

// Scratch (allocation-free rule: __device__ globals)
__device__ float g_gates[(size_t)M_ * N3_];        // activated z|f|o, 192 MB
__device__ float g_cend [B_ * NCHUNK * U_];
__device__ float g_P    [B_ * NCHUNK * U_];
__device__ float g_cst  [B_ * NCHUNK * U_];

// ---------------------------------------------------------------------------
// Kernel 1: gates GEMM + activation epilogue
// A[m][k] : k<512 -> x[b, t-1, k] (0 if t==0) ; k>=512 -> x[b, t, k-512]
// B[k][n] : kernel flattened [1024,1536] (contiguous, window-major)
// ---------------------------------------------------------------------------
__global__ __launch_bounds__(256, 2) void gates_gemm(
    const float* __restrict__ x,
    const float* __restrict__ kern,
    const float* __restrict__ bias)
{
    __shared__ float As[BK * ASTRIDE];   // As[kloc*ASTRIDE + m]
    __shared__ float Bs[BK * BN];        // Bs[kloc*BN + n]

    const int tid  = threadIdx.x;
    const int col0 = blockIdx.x * BN;
    const int row0 = blockIdx.y * BM;
    const int tx = tid & 15;             // N direction (4 cols each)
    const int ty = tid >> 4;             // M direction (4 rows each)

    // A-tile loader mapping: one float4 per thread
    const int arow  = tid >> 2;          // 0..63
    const int acol4 = (tid & 3) << 2;    // 0,4,8,12
    const int m  = row0 + arow;
    const int t  = m & (T_ - 1);
    const int b  = m >> 12;
    const float* xprev = (t > 0) ? (x + (size_t)(b * T_ + t - 1) * D_) : nullptr;
    const float* xcur  = x + (size_t)(b * T_ + t) * D_;

    // B-tile loader mapping: one float4 per thread
    const int brow  = tid >> 4;          // 0..15
    const int bcol4 = (tid & 15) << 2;   // 0..60

    float acc[4][4] = {};

    for (int kk = 0; kk < K_; kk += BK) {
        // ---- load A tile (BM x BK) transposed into As[k][m]
        {
            const int k = kk + acol4;
            float4 av;
            if (k < D_) {
                av = xprev ? *(const float4*)(xprev + k) : make_float4(0.f, 0.f, 0.f, 0.f);
            } else {
                av = *(const float4*)(xcur + (k - D_));
            }
            As[(acol4 + 0) * ASTRIDE + arow] = av.x;
            As[(acol4 + 1) * ASTRIDE + arow] = av.y;
            As[(acol4 + 2) * ASTRIDE + arow] = av.z;
            As[(acol4 + 3) * ASTRIDE + arow] = av.w;
        }
        // ---- load B tile (BK x BN)
        {
            const float4 bv = *(const float4*)(kern + (size_t)(kk + brow) * N3_ + col0 + bcol4);
            *(float4*)(&Bs[brow * BN + bcol4]) = bv;
        }
        __syncthreads();

        #pragma unroll
        for (int k = 0; k < BK; k++) {
            const float4 a = *(const float4*)(&As[k * ASTRIDE + (ty << 2)]);
            const float4 v = *(const float4*)(&Bs[k * BN + (tx << 2)]);
            const float ar[4] = {a.x, a.y, a.z, a.w};
            const float br[4] = {v.x, v.y, v.z, v.w};
            #pragma unroll
            for (int i = 0; i < 4; i++)
                #pragma unroll
                for (int j = 0; j < 4; j++)
                    acc[i][j] = fmaf(ar[i], br[j], acc[i][j]);
        }
        __syncthreads();
    }

    // ---- epilogue: bias + activation, float4 stores
    // col0 is a multiple of 64; gate-region boundaries (512,1024) are multiples
    // of 64, so the whole block uses one activation type.
    const bool is_tanh = (col0 < U_);
    #pragma unroll
    for (int i = 0; i < 4; i++) {
        const int mm = row0 + (ty << 2) + i;
        const int nn = col0 + (tx << 2);
        float4 g;
        g.x = acc[i][0] + bias[nn + 0];
        g.y = acc[i][1] + bias[nn + 1];
        g.z = acc[i][2] + bias[nn + 2];
        g.w = acc[i][3] + bias[nn + 3];
        float4 r;
        if (is_tanh) {
            r.x = tanhf(g.x); r.y = tanhf(g.y); r.z = tanhf(g.z); r.w = tanhf(g.w);
        } else {
            r.x = 1.f / (1.f + expf(-g.x));
            r.y = 1.f / (1.f + expf(-g.y));
            r.z = 1.f / (1.f + expf(-g.z));
            r.w = 1.f / (1.f + expf(-g.w));
        }
        *(float4*)(&g_gates[(size_t)mm * N3_ + nn]) = r;
    }
}

// ---------------------------------------------------------------------------
// Scan pass 1: per (b, chunk, u) compute homogeneous chunk scan from c=0 and
// the f-product across the chunk.
// ---------------------------------------------------------------------------
__global__ __launch_bounds__(256) void scan_pass1()
{
    const int idx   = blockIdx.x * blockDim.x + threadIdx.x;  // b*16384 + chunk*512 + u
    const int u     = idx & (U_ - 1);
    const int chunk = (idx >> 9) & (NCHUNK - 1);
    const int b     = idx >> 14;

    size_t base = (size_t)(b * T_ + chunk * TCHUNK) * N3_ + u;
    float c = 0.f, P = 1.f;
    #pragma unroll 4
    for (int s = 0; s < TCHUNK; s++) {
        const float z = g_gates[base];
        const float f = g_gates[base + U_];
        c = fmaf(f, c, (1.f - f) * z);
        P *= f;
        base += N3_;
    }
    g_cend[idx] = c;
    g_P[idx]    = P;
}

// ---------------------------------------------------------------------------
// Scan pass 2: tiny sequential combine over chunks (4096 lanes x 32 steps).
// c_after = c_hom + P * c_before
// ---------------------------------------------------------------------------
__global__ __launch_bounds__(256) void scan_pass2()
{
    const int idx = blockIdx.x * blockDim.x + threadIdx.x;    // 0..4095
    const int u   = idx & (U_ - 1);
    const int b   = idx >> 9;
    float c = 0.f;
    #pragma unroll
    for (int chunk = 0; chunk < NCHUNK; chunk++) {
        const int o = (b * NCHUNK + chunk) * U_ + u;
        g_cst[o] = c;
        c = fmaf(g_P[o], c, g_cend[o]);
    }
}

// ---------------------------------------------------------------------------
// Scan pass 3: re-scan each chunk with the correct carry-in, emit y = o * c.
// ---------------------------------------------------------------------------
__global__ __launch_bounds__(256) void scan_pass3(float* __restrict__ out)
{
    const int idx   = blockIdx.x * blockDim.x + threadIdx.x;
    const int u     = idx & (U_ - 1);
    const int chunk = (idx >> 9) & (NCHUNK - 1);
    const int b     = idx >> 14;

    size_t base  = (size_t)(b * T_ + chunk * TCHUNK) * N3_ + u;
    size_t obase = (size_t)(b * T_ + chunk * TCHUNK) * U_ + u;
    float c = g_cst[idx];
    #pragma unroll 4
    for (int s = 0; s < TCHUNK; s++) {
        const float z = g_gates[base];
        const float f = g_gates[base + U_];
        const float o = g_gates[base + 2 * U_];
        c = fmaf(f, c, (1.f - f) * z);
        out[obase] = o * c;
        base  += N3_;
        obase += U_;
    }
}

// ---------------------------------------------------------------------------
extern "C" void kernel_launch(void* const* d_in, const int* in_sizes, int n_in,
                              void* d_out, int out_size)
{
    const float* x    = (const float*)d_in[0];   // [8,4096,512]
    const float* kern = (const float*)d_in[1];   // [2,512,1536] -> [1024,1536]
    const float* bias = (const float*)d_in[2];   // [1536]
    float* out = (float*)d_out;                  // [8,4096,512]

    dim3 ggrid(N3_ / BN, M_ / BM);               // (24, 512)
    gates_gemm<<<ggrid, 256>>>(x, kern, bias);

    scan_pass1<<<(B_ * NCHUNK * U_) / 256, 256>>>();
    scan_pass2<<<(B_ * U_) / 256, 256>>>();
    scan_pass3<<<(B_ * NCHUNK * U_) / 256, 256>>>(out);
}

// round 3
// speedup vs baseline: 2.2428x; 2.2428x over previous
#include <cuda_runtime.h>
#include <cuda_bf16.h>
#include <stdint.h>
#include <math.h>

// ---------------------------------------------------------------------------
// QRNN on sm_103 (family target: no tcgen05 available in this harness).
// gates GEMM (M=32768, N=1536, K=1024) via mma.sync bf16 hi/lo 3-way split,
// then fo-pool chunked scan.
// ---------------------------------------------------------------------------

#define B_   8
#define T_   4096
#define D_   512
#define U_   512
#define N3_  1536
#define K_   1024
#define M_   (B_*T_)

#define BM 128
#define BN 128
#define BK 32
#define KCHUNKS (K_/BK)          // 32
#define STAGES 4

#define PITCH       40           // bf16 elems per smem row (80 B)
#define ROWB        80
#define MAT_BYTES   (128*ROWB)               // 10240
#define STAGE_BYTES (4*MAT_BYTES)            // 40960
#define SMEM_TOTAL  (STAGES*STAGE_BYTES)     // 163840

#define NCHUNK 32
#define TCHUNK (T_/NCHUNK)       // 128

// ---- scratch ----------------------------------------------------------------
__device__ float g_gates[(size_t)M_ * N3_];
__device__ float g_cend [B_*NCHUNK*U_];
__device__ float g_P    [B_*NCHUNK*U_];
__device__ float g_cst  [B_*NCHUNK*U_];
__device__ __nv_bfloat16 g_xhi[(size_t)M_ * D_];
__device__ __nv_bfloat16 g_xlo[(size_t)M_ * D_];
__device__ __nv_bfloat16 g_khi[(size_t)N3_ * K_];   // transposed [N,K]
__device__ __nv_bfloat16 g_klo[(size_t)N3_ * K_];

// ---- helpers ------------------------------------------------------------------
__device__ __forceinline__ uint32_t smem_u32(const void* p) {
    uint32_t r;
    asm("{ .reg .u64 t; cvta.to.shared.u64 t, %1; cvt.u32.u64 %0, t; }" : "=r"(r) : "l"(p));
    return r;
}
__device__ __forceinline__ void cp16(uint32_t dst, const void* src, int ssize) {
    asm volatile("cp.async.cg.shared.global [%0], [%1], 16, %2;"
                 :: "r"(dst), "l"(src), "r"(ssize) : "memory");
}
__device__ __forceinline__ void ldm_x4(uint32_t* r, uint32_t addr) {
    asm volatile("ldmatrix.sync.aligned.m8n8.x4.shared.b16 {%0,%1,%2,%3}, [%4];"
                 : "=r"(r[0]), "=r"(r[1]), "=r"(r[2]), "=r"(r[3]) : "r"(addr));
}
__device__ __forceinline__ void mma16816(float* d, const uint32_t* a,
                                         uint32_t b0, uint32_t b1) {
    asm volatile(
        "mma.sync.aligned.m16n8k16.row.col.f32.bf16.bf16.f32 "
        "{%0,%1,%2,%3},{%4,%5,%6,%7},{%8,%9},{%0,%1,%2,%3};"
        : "+f"(d[0]), "+f"(d[1]), "+f"(d[2]), "+f"(d[3])
        : "r"(a[0]), "r"(a[1]), "r"(a[2]), "r"(a[3]), "r"(b0), "r"(b1));
}
__device__ __forceinline__ float sigf(float x) {
    float e = __expf(-x);
    float d = 1.f + e, r;
    asm("rcp.approx.f32 %0, %1;" : "=f"(r) : "f"(d));
    return r;
}
__device__ __forceinline__ float tanhf_fast(float x) {
    return 2.f * sigf(2.f * x) - 1.f;
}

// ---------------------------------------------------------------------------
// fp32 -> bf16 hi/lo converters
// ---------------------------------------------------------------------------
__global__ __launch_bounds__(256) void convert_x(const float* __restrict__ x) {
    size_t i = ((size_t)blockIdx.x * blockDim.x + threadIdx.x) * 4;
    float4 v = *(const float4*)(x + i);
    __nv_bfloat16 h[4], l[4];
    float vv[4] = {v.x, v.y, v.z, v.w};
    #pragma unroll
    for (int j = 0; j < 4; j++) {
        h[j] = __float2bfloat16_rn(vv[j]);
        l[j] = __float2bfloat16_rn(vv[j] - __bfloat162float(h[j]));
    }
    *(uint2*)(g_xhi + i) = *(uint2*)h;
    *(uint2*)(g_xlo + i) = *(uint2*)l;
}

__global__ __launch_bounds__(256) void convert_k(const float* __restrict__ kern) {
    int idx = blockIdx.x * blockDim.x + threadIdx.x;   // over N3_*K_
    int n = idx >> 10;
    int k = idx & (K_ - 1);
    float v = kern[(size_t)k * N3_ + n];
    __nv_bfloat16 h = __float2bfloat16_rn(v);
    g_khi[idx] = h;
    g_klo[idx] = __float2bfloat16_rn(v - __bfloat162float(h));
}

// ---------------------------------------------------------------------------
// HMMA GEMM: D = Ah*Bh + Ah*Bl + Al*Bh  (fp32 accum), + bias + activation.
// A[m][k]: k<512 -> x[b,t-1,k] (0 at t==0), else x[b,t,k-512]
// smem tiles: 4 matrices (Ah,Al,Bh,Bl) of [128][PITCH] bf16 per stage.
// ---------------------------------------------------------------------------
__global__ __launch_bounds__(256, 1)
void gates_gemm_hmma(const float* __restrict__ bias)
{
    extern __shared__ char smem[];
    const uint32_t sb = smem_u32(smem);

    const int tid  = threadIdx.x;
    const int wid  = tid >> 5;
    const int lane = tid & 31;
    const int m0 = blockIdx.y * BM;
    const int n0 = blockIdx.x * BN;

    const int warp_m = wid >> 2;         // 0..1
    const int warp_n = wid & 3;          // 0..3
    const int wm = warp_m * 64;
    const int wn = warp_n * 32;

    // ---- loader mapping: each thread owns one row (A & B) and 2 x 16B segs
    const int arow = tid >> 1;           // 0..127
    const int seg0 = (tid & 1) * 2;      // 0 or 2
    const int mg = m0 + arow;
    const int tt = mg & (T_ - 1);
    const int avalid = (tt != 0);
    const size_t a_prev = avalid ? (size_t)(mg - 1) * D_ : 0;
    const size_t a_cur  = (size_t)mg * D_;
    const size_t b_off  = (size_t)(n0 + arow) * K_;
    const uint32_t dstRow = (uint32_t)(arow * ROWB);

#define LOAD_STAGE(I) do {                                                    \
        const int s_ = (I) % STAGES;                                          \
        const int kk_ = (I) * BK;                                             \
        const bool fh_ = (kk_ < 512);                                         \
        const __nv_bfloat16* sxh_; const __nv_bfloat16* sxl_; int asz_;       \
        if (fh_) { sxh_ = g_xhi + a_prev + kk_; sxl_ = g_xlo + a_prev + kk_;  \
                   asz_ = avalid ? 16 : 0; }                                  \
        else     { sxh_ = g_xhi + a_cur + kk_ - 512;                          \
                   sxl_ = g_xlo + a_cur + kk_ - 512; asz_ = 16; }             \
        const __nv_bfloat16* sbh_ = g_khi + b_off + kk_;                      \
        const __nv_bfloat16* sbl_ = g_klo + b_off + kk_;                      \
        const uint32_t d_ = sb + s_ * STAGE_BYTES + dstRow;                   \
        _Pragma("unroll")                                                     \
        for (int j_ = 0; j_ < 2; j_++) {                                      \
            const int sg_ = seg0 + j_;                                        \
            cp16(d_ + 0*MAT_BYTES + sg_*16, sxh_ + sg_*8, asz_);              \
            cp16(d_ + 1*MAT_BYTES + sg_*16, sxl_ + sg_*8, asz_);              \
            cp16(d_ + 2*MAT_BYTES + sg_*16, sbh_ + sg_*8, 16);                \
            cp16(d_ + 3*MAT_BYTES + sg_*16, sbl_ + sg_*8, 16);                \
        }                                                                     \
        asm volatile("cp.async.commit_group;" ::: "memory");                  \
    } while (0)

    // ---- ldmatrix per-lane base offsets (byte offsets within a matrix tile)
    const uint32_t aRowB = (uint32_t)((wm + (lane & 15)) * ROWB + ((lane >> 4) * 16));
    const uint32_t bRowB = (uint32_t)((wn + ((lane >> 4) & 1) * 8 + (lane & 7)) * ROWB
                                      + (((lane >> 3) & 1) * 16));

    float acc[4][4][4];
    #pragma unroll
    for (int i = 0; i < 4; i++)
        #pragma unroll
        for (int j = 0; j < 4; j++)
            #pragma unroll
            for (int q = 0; q < 4; q++) acc[i][j][q] = 0.f;

    // ---- prologue: prefetch STAGES-1 stages
    #pragma unroll
    for (int i = 0; i < STAGES - 1; i++) LOAD_STAGE(i);

    // ---- main loop
    for (int i = 0; i < KCHUNKS; i++) {
        asm volatile("cp.async.wait_group %0;" :: "n"(STAGES - 2));
        __syncthreads();

        if (i + STAGES - 1 < KCHUNKS) {
            LOAD_STAGE(i + STAGES - 1);
        } else {
            asm volatile("cp.async.commit_group;" ::: "memory");
        }

        const int s = i % STAGES;
        const uint32_t stg = sb + s * STAGE_BYTES;

        #pragma unroll
        for (int ks = 0; ks < 2; ks++) {
            const uint32_t kb = ks * 32;    // byte offset of k-halfstep (16 elems)
            uint32_t ah[4][4], al[4][4], bh[2][4], bl[2][4];
            #pragma unroll
            for (int mi = 0; mi < 4; mi++) {
                ldm_x4(ah[mi], stg + 0*MAT_BYTES + aRowB + mi*16*ROWB + kb);
                ldm_x4(al[mi], stg + 1*MAT_BYTES + aRowB + mi*16*ROWB + kb);
            }
            #pragma unroll
            for (int np = 0; np < 2; np++) {
                ldm_x4(bh[np], stg + 2*MAT_BYTES + bRowB + np*16*ROWB + kb);
                ldm_x4(bl[np], stg + 3*MAT_BYTES + bRowB + np*16*ROWB + kb);
            }
            #pragma unroll
            for (int mi = 0; mi < 4; mi++) {
                #pragma unroll
                for (int nj = 0; nj < 4; nj++) {
                    const int np = nj >> 1, h = (nj & 1) * 2;
                    mma16816(acc[mi][nj], ah[mi], bh[np][h], bh[np][h+1]);
                    mma16816(acc[mi][nj], ah[mi], bl[np][h], bl[np][h+1]);
                    mma16816(acc[mi][nj], al[mi], bh[np][h], bh[np][h+1]);
                }
            }
        }
        __syncthreads();
    }

    // ---- epilogue: bias + activation -> g_gates (f32)
    const bool is_tanh = (n0 < U_);
    #pragma unroll
    for (int nj = 0; nj < 4; nj++) {
        const int c = n0 + wn + nj * 8 + (lane & 3) * 2;
        const float b0 = __ldg(bias + c);
        const float b1 = __ldg(bias + c + 1);
        #pragma unroll
        for (int mi = 0; mi < 4; mi++) {
            const int r = m0 + wm + mi * 16 + (lane >> 2);
            float* p0 = g_gates + (size_t)r * N3_ + c;
            float* p1 = g_gates + (size_t)(r + 8) * N3_ + c;
            float2 v0, v1;
            v0.x = acc[mi][nj][0] + b0; v0.y = acc[mi][nj][1] + b1;
            v1.x = acc[mi][nj][2] + b0; v1.y = acc[mi][nj][3] + b1;
            if (is_tanh) {
                v0.x = tanhf_fast(v0.x); v0.y = tanhf_fast(v0.y);
                v1.x = tanhf_fast(v1.x); v1.y = tanhf_fast(v1.y);
            } else {
                v0.x = sigf(v0.x); v0.y = sigf(v0.y);
                v1.x = sigf(v1.x); v1.y = sigf(v1.y);
            }
            *(float2*)p0 = v0;
            *(float2*)p1 = v1;
        }
    }
#undef LOAD_STAGE
}

// ---------------------------------------------------------------------------
// fo-pool chunked scan (3 passes)
// ---------------------------------------------------------------------------
__global__ __launch_bounds__(256) void scan_pass1()
{
    const int idx   = blockIdx.x * blockDim.x + threadIdx.x;
    const int u     = idx & (U_ - 1);
    const int chunk = (idx >> 9) & (NCHUNK - 1);
    const int b     = idx >> 14;

    size_t base = (size_t)(b * T_ + chunk * TCHUNK) * N3_ + u;
    float c = 0.f, P = 1.f;
    #pragma unroll 4
    for (int s = 0; s < TCHUNK; s++) {
        const float z = g_gates[base];
        const float f = g_gates[base + U_];
        c = fmaf(f, c, (1.f - f) * z);
        P *= f;
        base += N3_;
    }
    g_cend[idx] = c;
    g_P[idx]    = P;
}

__global__ __launch_bounds__(256) void scan_pass2()
{
    const int idx = blockIdx.x * blockDim.x + threadIdx.x;    // 0..4095
    const int u   = idx & (U_ - 1);
    const int b   = idx >> 9;
    float c = 0.f;
    #pragma unroll
    for (int chunk = 0; chunk < NCHUNK; chunk++) {
        const int o = (b * NCHUNK + chunk) * U_ + u;
        g_cst[o] = c;
        c = fmaf(g_P[o], c, g_cend[o]);
    }
}

__global__ __launch_bounds__(256) void scan_pass3(float* __restrict__ out)
{
    const int idx   = blockIdx.x * blockDim.x + threadIdx.x;
    const int u     = idx & (U_ - 1);
    const int chunk = (idx >> 9) & (NCHUNK - 1);
    const int b     = idx >> 14;

    size_t base  = (size_t)(b * T_ + chunk * TCHUNK) * N3_ + u;
    size_t obase = (size_t)(b * T_ + chunk * TCHUNK) * U_ + u;
    float c = g_cst[idx];
    #pragma unroll 4
    for (int s = 0; s < TCHUNK; s++) {
        const float z = g_gates[base];
        const float f = g_gates[base + U_];
        const float o = g_gates[base + 2*U_];
        c = fmaf(f, c, (1.f - f) * z);
        out[obase] = o * c;
        base  += N3_;
        obase += U_;
    }
}

// ---------------------------------------------------------------------------
extern "C" void kernel_launch(void* const* d_in, const int* in_sizes, int n_in,
                              void* d_out, int out_size)
{
    const float* x    = (const float*)d_in[0];
    const float* kern = (const float*)d_in[1];
    const float* bias = (const float*)d_in[2];
    float* out = (float*)d_out;

    cudaFuncSetAttribute(gates_gemm_hmma,
                         cudaFuncAttributeMaxDynamicSharedMemorySize, SMEM_TOTAL);

    convert_x<<<(M_ * D_ / 4) / 256, 256>>>(x);
    convert_k<<<(N3_ * K_) / 256, 256>>>(kern);

    dim3 ggrid(N3_ / BN, M_ / BM);   // (12, 256)
    gates_gemm_hmma<<<ggrid, 256, SMEM_TOTAL>>>(bias);

    scan_pass1<<<(B_ * NCHUNK * U_) / 256, 256>>>();
    scan_pass2<<<(B_ * U_) / 256, 256>>>();
    scan_pass3<<<(B_ * NCHUNK * U_) / 256, 256>>>(out);
}